// round 7
// baseline (speedup 1.0000x reference)
#include <cuda_runtime.h>
#include <cuda_bf16.h>
#include <math.h>

typedef unsigned int uint;

#define S 128
#define T 128
#define NB 16
#define NH 64
#define DH 128
#define TS 15
#define NS 16
#define NTILE 9
#define TPB 512
#define TOUT 107
#define NSTEP 127

// Fragment-ordered bf16 weights: entry (kt,nt,lane) = {b0, b1}
__device__ uint2 fBn[12*32*32];
__device__ uint2 fBs[12*32*32];
__device__ uint2 fBd[32*64*32];

// Boundary publish ring: [buf][g][tile][bp][slot][256]
//   slot0 = site s0 (for left neighbor), slot1 = site s0+13 (for right neighbor)
//   entry: [0:64) hn, [64:128) hs, [128:256) hd
__device__ float g_pub[2][8][NTILE][2][2][256];
__device__ int g_flag[8*NTILE];

// ---- smem offsets (floats) ----
#define OFF_XIN 0                      // 2*64
#define OFF_O0  (OFF_XIN + 128)        // 2*16
#define OFF_O1  (OFF_O0 + 32)          // 2*16
#define OFF_CN  (OFF_O1 + 32)          // 2*1024
#define OFF_CS  (OFF_CN + 2048)        // 2*1024
#define OFF_CD  (OFF_CS + 2048)        // 2*2048
#define OFF_HDC (OFF_CD + 4096)        // 2*2048
#define OFF_NSF (OFF_HDC + 4096)       // 6144 uints (An/As per bp)
#define OFF_ADF (OFF_NSF + 6144)       // 8192 uints (Ad per bp)
#define OFF_G   (OFF_ADF + 8192)       // 16384 (gn/gs; gd overlay)
#define SMEM_FLOATS (OFF_G + 16384)

#define MMA4(c, a0,a1,a2,a3, b0,b1) \
  asm volatile("mma.sync.aligned.m16n8k16.row.col.f32.bf16.bf16.f32 " \
    "{%0,%1,%2,%3}, {%4,%5,%6,%7}, {%8,%9}, {%0,%1,%2,%3};" \
    : "+f"(c[0]), "+f"(c[1]), "+f"(c[2]), "+f"(c[3]) \
    : "r"(a0), "r"(a1), "r"(a2), "r"(a3), "r"(b0), "r"(b1))

__device__ __forceinline__ float sigm(float x) { return 1.f / (1.f + __expf(-x)); }

__device__ __forceinline__ uint packbf2(float a, float b) {
    __nv_bfloat16 ha = __float2bfloat16_rn(a);
    __nv_bfloat16 hb = __float2bfloat16_rn(b);
    __nv_bfloat16_raw ra = *(__nv_bfloat16_raw*)&ha;
    __nv_bfloat16_raw rb = *(__nv_bfloat16_raw*)&hb;
    return (uint)ra.x | ((uint)rb.x << 16);
}

// write one bf16 element into fragment-ordered array at logical (row r, col k)
__device__ __forceinline__ void store_frag(__nv_bfloat16* Fb, int r, int k, float v) {
    int kt = k >> 4, ec = k & 15;
    int reg = ((ec >> 3) << 1) | (r >> 3);
    int ln  = ((r & 7) << 2) | ((ec & 7) >> 1);
    int idx = ((((kt << 5) + ln) << 2) + reg) * 2 + (ec & 1);
    Fb[idx] = __float2bfloat16_rn(v);
}

__global__ void init_flags_kernel() {
    int i = blockIdx.x * blockDim.x + threadIdx.x;
    if (i < 8*NTILE) g_flag[i] = 0;
}

__global__ void repack_kernel(
    const float* __restrict__ nWh, const float* __restrict__ nWa, const float* __restrict__ nWb,
    const float* __restrict__ sWh, const float* __restrict__ sWa, const float* __restrict__ sWb,
    const float* __restrict__ dWx, const float* __restrict__ dWh,
    const float* __restrict__ dWa, const float* __restrict__ dWb)
{
    int idx = blockIdx.x * blockDim.x + threadIdx.x;
    if (idx < 32*64*32) {
        int lane = idx & 31, nt = (idx >> 5) & 63, kt = idx >> 11;
        int n = nt*8 + (lane >> 2);
        int k0 = kt*16 + (lane & 3)*2;
        float v[4];
        #pragma unroll
        for (int j = 0; j < 4; j++) {
            int kk = k0 + (j >> 1)*8 + (j & 1);
            float x;
            if      (kk < 128) x = dWx[kk*512 + n];
            else if (kk < 256) x = dWh[(kk-128)*512 + n];
            else if (kk < 384) x = dWa[(kk-256)*512 + n];
            else               x = dWb[(kk-384)*512 + n];
            v[j] = x;
        }
        fBd[idx] = make_uint2(packbf2(v[0], v[1]), packbf2(v[2], v[3]));
    }
    int idx2 = idx - 32*64*32;
    if (idx2 >= 0 && idx2 < 2*12*32*32) {
        int set = idx2 / (12*32*32);
        int e = idx2 % (12*32*32);
        int lane = e & 31, nt = (e >> 5) & 31, kt = e >> 10;
        int n = nt*8 + (lane >> 2);
        int k0 = kt*16 + (lane & 3)*2;
        const float* Wh = set ? sWh : nWh;
        const float* Wa = set ? sWa : nWa;
        const float* Wb = set ? sWb : nWb;
        float v[4];
        #pragma unroll
        for (int j = 0; j < 4; j++) {
            int kk = k0 + (j >> 1)*8 + (j & 1);
            float x;
            if      (kk < 64)  x = Wh[kk*256 + n];
            else if (kk < 128) x = Wa[(kk-64)*256 + n];
            else               x = Wb[(kk-128)*256 + n];
            v[j] = x;
        }
        (set ? fBs : fBn)[e] = make_uint2(packbf2(v[0], v[1]), packbf2(v[2], v[3]));
    }
}

__global__ void __launch_bounds__(TPB, 1) persistent_kernel(
    const float* __restrict__ xg,
    const float* __restrict__ nWx, const float* __restrict__ nb,
    const float* __restrict__ sWx, const float* __restrict__ sb,
    const float* __restrict__ db,
    const float* __restrict__ onW, const float* __restrict__ onb,
    const float* __restrict__ osW, const float* __restrict__ osb,
    float* __restrict__ out)
{
    extern __shared__ float sm[];
    float* xin = sm + OFF_XIN;   // [bp][16][4]
    float* o0s = sm + OFF_O0;    // [bp][16]
    float* o1s = sm + OFF_O1;
    float* cns = sm + OFF_CN;    // [bp][16*64]
    float* css = sm + OFF_CS;
    float* cds = sm + OFF_CD;    // [bp][16*128]
    float* hdc = sm + OFF_HDC;   // [bp][16*128]
    uint*  nsU = (uint*)(sm + OFF_NSF);
    uint4* nsF4 = (uint4*)(sm + OFF_NSF);   // bp stride 768 uint4; set stride 384
    uint*  adU = (uint*)(sm + OFF_ADF);
    uint4* AdF4 = (uint4*)(sm + OFF_ADF);   // bp stride 1024 uint4
    float* G = sm + OFF_G;       // gn(bp)=bp*8192, gs=+4096; gd overlay bp*8192

    const int tid  = threadIdx.x;
    const int w    = tid >> 5;
    const int lane = tid & 31;
    const int tile = blockIdx.x;      // 0..8
    const int g    = blockIdx.y;      // 0..7 (batch pair)
    const int s0   = tile * TS;

    // ---- persistent-state init ----
    for (int i = tid; i < 6144; i += TPB) nsU[i] = 0;
    for (int i = tid; i < 8192; i += TPB) adU[i] = 0;
    for (int i = tid; i < 2048; i += TPB) { cns[i] = 0.f; css[i] = 0.f; }
    for (int i = tid; i < 4096; i += TPB) cds[i] = 0.f;
    __syncthreads();

    for (int t = 0; t < NSTEP; ++t) {
        // ---- P0: neighbor flag wait, halo import, xin load ----
        if (t > 0) {
            if (tid == 0 && tile > 0) {
                volatile int* f = &g_flag[g*NTILE + tile - 1];
                while (*f < t) {}
                __threadfence();
            }
            if (tid == 32 && tile < NTILE-1) {
                volatile int* f = &g_flag[g*NTILE + tile + 1];
                while (*f < t) {}
                __threadfence();
            }
        }
        __syncthreads();

        if (t > 0) {
            const int pb = (t - 1) & 1;
            if (tile > 0) {  // left slot1 = site s0-2
                for (int u = tid; u < 2*64; u += TPB) {
                    int bp = u >> 6, e = u & 63;
                    const float* L = g_pub[pb][g][tile-1][bp][1];
                    __nv_bfloat16* AnB = (__nv_bfloat16*)nsU + bp*6144;
                    store_frag(AnB, 0, 128+e, L[e]);
                    store_frag(AnB + 3072, 0, 128+e, L[64+e]);
                }
                for (int u = tid; u < 2*128; u += TPB) {
                    int bp = u >> 7, e = u & 127;
                    const float* L = g_pub[pb][g][tile-1][bp][1];
                    store_frag((__nv_bfloat16*)adU + bp*8192, 0, 384+e, L[128+e]);
                }
            }
            if (tile < NTILE-1) {  // right slot0 = site s0+15
                for (int u = tid; u < 2*64; u += TPB) {
                    int bp = u >> 6, e = u & 63;
                    const float* R = g_pub[pb][g][tile+1][bp][0];
                    __nv_bfloat16* AnB = (__nv_bfloat16*)nsU + bp*6144;
                    store_frag(AnB, 15, 64+e, R[e]);
                    store_frag(AnB + 3072, 15, 64+e, R[64+e]);
                }
                for (int u = tid; u < 2*128; u += TPB) {
                    int bp = u >> 7, e = u & 127;
                    const float* R = g_pub[pb][g][tile+1][bp][0];
                    store_frag((__nv_bfloat16*)adU + bp*8192, 15, 256+e, R[128+e]);
                }
            }
        }
        for (int i = tid; i < 2*NS*4; i += TPB) {
            int bp = i >> 6, j = i & 63;
            int r = j >> 2, sg = s0 - 1 + r;
            int bb = g*2 + bp;
            xin[i] = ((unsigned)sg < (unsigned)S)
                     ? xg[(((size_t)bb*T + t)*S + sg)*4 + (j & 3)] : 0.f;
        }
        __syncthreads();

        // ---- P1: ns GEMM (both batches) + d GEMM part 1 (kt 8..31) ----
        float dacc[2][4][4];
        #pragma unroll
        for (int bp = 0; bp < 2; bp++)
            #pragma unroll
            for (int j = 0; j < 4; j++)
                #pragma unroll
                for (int c = 0; c < 4; c++) dacc[bp][j][c] = 0.f;
        {
            const int set = w >> 3, grp = w & 7;
            const uint2* Bns = set ? fBs : fBn;
            const uint4* A0 = nsF4 + set*384;
            const uint4* A1 = A0 + 768;
            float acc[2][4][4];
            #pragma unroll
            for (int bp = 0; bp < 2; bp++)
                #pragma unroll
                for (int j = 0; j < 4; j++)
                    #pragma unroll
                    for (int c = 0; c < 4; c++) acc[bp][j][c] = 0.f;

            for (int kt = 0; kt < 12; kt++) {
                uint4 a0 = A0[kt*32 + lane];
                uint4 a1 = A1[kt*32 + lane];
                #pragma unroll
                for (int j = 0; j < 4; j++) {
                    uint2 bv = __ldg(&Bns[(kt*32 + grp*4 + j)*32 + lane]);
                    MMA4(acc[0][j], a0.x, a0.y, a0.z, a0.w, bv.x, bv.y);
                    MMA4(acc[1][j], a1.x, a1.y, a1.z, a1.w, bv.x, bv.y);
                }
            }
            int site0 = lane >> 2, cb = (lane & 3)*2;
            #pragma unroll
            for (int bp = 0; bp < 2; bp++) {
                float* gg = G + bp*8192 + set*4096;
                #pragma unroll
                for (int j = 0; j < 4; j++) {
                    int c0 = (grp*4 + j)*8 + cb;
                    *(float2*)&gg[site0*256 + c0]     = make_float2(acc[bp][j][0], acc[bp][j][1]);
                    *(float2*)&gg[(site0+8)*256 + c0] = make_float2(acc[bp][j][2], acc[bp][j][3]);
                }
            }
            for (int kt = 8; kt < 32; kt++) {
                uint4 a0 = AdF4[kt*32 + lane];
                uint4 a1 = AdF4[1024 + kt*32 + lane];
                #pragma unroll
                for (int j = 0; j < 4; j++) {
                    uint2 bv = __ldg(&fBd[(kt*64 + w*4 + j)*32 + lane]);
                    MMA4(dacc[0][j], a0.x, a0.y, a0.z, a0.w, bv.x, bv.y);
                    MMA4(dacc[1][j], a1.x, a1.y, a1.z, a1.w, bv.x, bv.y);
                }
            }
        }
        __syncthreads();

        // ---- P2: n/s cell updates; write next-step ns frags + Ad(k<128) + pubs ----
        for (int i = tid; i < 2*NS*NH; i += TPB) {
            int bp = i >> 10, j = i & 1023;
            int r = j >> 6, e = j & 63;
            int sg = s0 - 1 + r;
            bool v = ((unsigned)sg < (unsigned)S);
            float* gn_ = G + bp*8192;
            float* gs_ = gn_ + 4096;
            const float* xr = xin + bp*64 + r*4;
            float xr0 = xr[0], xr1 = xr[1], xr2 = xr[2], xr3 = xr[3];
            __nv_bfloat16* AnB = (__nv_bfloat16*)nsU + bp*6144;
            __nv_bfloat16* AsB = AnB + 3072;
            __nv_bfloat16* AdB = (__nv_bfloat16*)adU + bp*8192;
            float hn_, hs_;
            {
                float ii = gn_[r*256 + e]      + nb[e]      + xr0*nWx[e]      + xr1*nWx[256+e]  + xr2*nWx[512+e];
                float ff = gn_[r*256 + 64+e]   + nb[64+e]   + xr0*nWx[64+e]   + xr1*nWx[320+e]  + xr2*nWx[576+e];
                float uu = gn_[r*256 + 128+e]  + nb[128+e]  + xr0*nWx[128+e]  + xr1*nWx[384+e]  + xr2*nWx[640+e];
                float oo = gn_[r*256 + 192+e]  + nb[192+e]  + xr0*nWx[192+e]  + xr1*nWx[448+e]  + xr2*nWx[704+e];
                float cp = cns[bp*1024 + j];
                float c2 = sigm(ff)*cp + sigm(ii)*tanhf(uu);
                float hh = sigm(oo)*tanhf(c2);
                if (!v) { c2 = 0.f; hh = 0.f; }
                cns[bp*1024 + j] = c2;
                hn_ = hh;
            }
            {
                float ii = gs_[r*256 + e]      + sb[e]      + xr3*sWx[e];
                float ff = gs_[r*256 + 64+e]   + sb[64+e]   + xr3*sWx[64+e];
                float uu = gs_[r*256 + 128+e]  + sb[128+e]  + xr3*sWx[128+e];
                float oo = gs_[r*256 + 192+e]  + sb[192+e]  + xr3*sWx[192+e];
                float cp = css[bp*1024 + j];
                float c2 = sigm(ff)*cp + sigm(ii)*tanhf(uu);
                float hh = sigm(oo)*tanhf(c2);
                if (!v) { c2 = 0.f; hh = 0.f; }
                css[bp*1024 + j] = c2;
                hs_ = hh;
            }
            // current-step d-GEMM inputs (k<128)
            store_frag(AdB, r, e, hn_);
            store_frag(AdB, r, 64+e, hs_);
            // next-step ns frags (3 shift positions each)
            store_frag(AnB, r, e, hn_);
            store_frag(AsB, r, e, hs_);
            if (r >= 1)  { store_frag(AnB, r-1, 64+e, hn_);  store_frag(AsB, r-1, 64+e, hs_); }
            if (r <= 14) { store_frag(AnB, r+1, 128+e, hn_); store_frag(AsB, r+1, 128+e, hs_); }
            // boundary publish
            if (r == 1)  { float* P = g_pub[t&1][g][tile][bp][0]; P[e] = hn_; P[64+e] = hs_; }
            if (r == 14) { float* P = g_pub[t&1][g][tile][bp][1]; P[e] = hn_; P[64+e] = hs_; }
        }
        __syncthreads();

        // ---- P3: d GEMM part 2 (kt 0..7), write gd (overlays gn/gs) ----
        {
            for (int kt = 0; kt < 8; kt++) {
                uint4 a0 = AdF4[kt*32 + lane];
                uint4 a1 = AdF4[1024 + kt*32 + lane];
                #pragma unroll
                for (int j = 0; j < 4; j++) {
                    uint2 bv = __ldg(&fBd[(kt*64 + w*4 + j)*32 + lane]);
                    MMA4(dacc[0][j], a0.x, a0.y, a0.z, a0.w, bv.x, bv.y);
                    MMA4(dacc[1][j], a1.x, a1.y, a1.z, a1.w, bv.x, bv.y);
                }
            }
        }
        __syncthreads();
        {
            int site0 = lane >> 2, cb = (lane & 3)*2;
            #pragma unroll
            for (int bp = 0; bp < 2; bp++) {
                float* gdp = G + bp*8192;
                #pragma unroll
                for (int j = 0; j < 4; j++) {
                    int c0 = (w*4 + j)*8 + cb;
                    *(float2*)&gdp[site0*512 + c0]     = make_float2(dacc[bp][j][0], dacc[bp][j][1]);
                    *(float2*)&gdp[(site0+8)*512 + c0] = make_float2(dacc[bp][j][2], dacc[bp][j][3]);
                }
            }
        }
        __syncthreads();

        // ---- P4: d cell update; write hdc + next-step Ad(k>=128) + pubs ----
        for (int i = tid; i < 2*NS*DH; i += TPB) {
            int bp = i >> 11, j = i & 2047;
            int r = j >> 7, e = j & 127;
            int sg = s0 - 1 + r;
            bool v = ((unsigned)sg < (unsigned)S);
            float* gdp = G + bp*8192;
            float ii = gdp[r*512 + e]       + db[e];
            float ff = gdp[r*512 + 128 + e] + db[128+e];
            float uu = gdp[r*512 + 256 + e] + db[256+e];
            float oo = gdp[r*512 + 384 + e] + db[384+e];
            float cp = cds[bp*2048 + j];
            float c2 = sigm(ff)*cp + sigm(ii)*tanhf(uu);
            float hh = sigm(oo)*tanhf(c2);
            if (!v) { c2 = 0.f; hh = 0.f; }
            cds[bp*2048 + j] = c2;
            hdc[bp*2048 + j] = hh;
            __nv_bfloat16* AdB = (__nv_bfloat16*)adU + bp*8192;
            store_frag(AdB, r, 128+e, hh);
            if (r >= 1)  store_frag(AdB, r-1, 256+e, hh);
            if (r <= 14) store_frag(AdB, r+1, 384+e, hh);
            if (r == 1)  g_pub[t&1][g][tile][bp][0][128+e] = hh;
            if (r == 14) g_pub[t&1][g][tile][bp][1][128+e] = hh;
        }
        __syncthreads();

        // flag release (pubs of step t complete)
        if (tid == 0) {
            __threadfence();
            *(volatile int*)&g_flag[g*NTILE + tile] = t + 1;
        }

        // ---- P5: output heads (64 warp-tasks over 16 warps) ----
        for (int task = w; task < 64; task += 16) {
            int bp = task >> 5;
            int which = (task >> 4) & 1;
            int r = task & 15;
            const float* W = which ? osW : onW;
            float a = 0.f;
            #pragma unroll
            for (int kk = lane; kk < DH; kk += 32) a += hdc[bp*2048 + r*DH + kk] * W[kk];
            #pragma unroll
            for (int d = 16; d >= 1; d >>= 1) a += __shfl_xor_sync(0xffffffffu, a, d);
            if (lane == 0) {
                if (which) o1s[bp*16 + r] = a + osb[0];
                else       o0s[bp*16 + r] = a + onb[0];
            }
        }
        __syncthreads();

        // ---- P6: write outputs for t >= 20 ----
        if (t >= 20) {
            int bp = tid >> 8, rr = tid & 255;
            if (rr >= 1 && rr <= TS) {
                int sg = s0 + rr - 1;
                if (sg < S) {
                    int bb = g*2 + bp;
                    float o0 = o0s[bp*16 + rr];
                    float o1 = o1s[bp*16 + rr];
                    float inflow, spd;
                    if (sg == 0) {
                        inflow = xg[(((size_t)bb*T + (t+1))*S + 0)*4 + 1];
                        spd    = xg[(((size_t)bb*T + (t+1))*S + 0)*4 + 3];
                    } else {
                        inflow = o0s[bp*16 + rr - 1];
                        spd    = o1;
                    }
                    float numc = xin[bp*64 + rr*4 + 2] + inflow - o0;
                    float* o = out + ((((size_t)bb*TOUT) + (t - 20))*S + sg)*4;
                    o[0] = o0; o[1] = inflow; o[2] = numc; o[3] = spd;
                }
            }
        }
        __syncthreads();
    }
}

extern "C" void kernel_launch(void* const* d_in, const int* in_sizes, int n_in,
                              void* d_out, int out_size) {
    const float* xg  = (const float*)d_in[0];
    const float* nWx = (const float*)d_in[1];
    const float* nWh = (const float*)d_in[2];
    const float* nWa = (const float*)d_in[3];
    const float* nWb = (const float*)d_in[4];
    const float* nb  = (const float*)d_in[5];
    const float* sWx = (const float*)d_in[6];
    const float* sWh = (const float*)d_in[7];
    const float* sWa = (const float*)d_in[8];
    const float* sWb = (const float*)d_in[9];
    const float* sb  = (const float*)d_in[10];
    const float* dWx = (const float*)d_in[11];
    const float* dWh = (const float*)d_in[12];
    const float* dWa = (const float*)d_in[13];
    const float* dWb = (const float*)d_in[14];
    const float* db  = (const float*)d_in[15];
    const float* onW = (const float*)d_in[16];
    const float* onb = (const float*)d_in[17];
    const float* osW = (const float*)d_in[18];
    const float* osb = (const float*)d_in[19];
    float* out = (float*)d_out;

    (void)in_sizes; (void)n_in; (void)out_size;

    const int smem_bytes = SMEM_FLOATS * (int)sizeof(float);
    cudaFuncSetAttribute(persistent_kernel,
                         cudaFuncAttributeMaxDynamicSharedMemorySize, smem_bytes);

    init_flags_kernel<<<1, 128>>>();
    int repack_threads = 32*64*32 + 2*12*32*32;
    repack_kernel<<<(repack_threads + 255) / 256, 256>>>(
        nWh, nWa, nWb, sWh, sWa, sWb, dWx, dWh, dWa, dWb);

    dim3 grid(NTILE, 8);
    persistent_kernel<<<grid, TPB, smem_bytes>>>(
        xg, nWx, nb, sWx, sb, db, onW, onb, osW, osb, out);
}

// round 8
// speedup vs baseline: 1.6400x; 1.6400x over previous
#include <cuda_runtime.h>
#include <cuda_bf16.h>
#include <math.h>

typedef unsigned int uint;

#define S 128
#define T 128
#define NB 16
#define NH 64
#define DH 128
#define TS 15
#define NS 16
#define NTILE 9
#define TPB 512
#define TOUT 107
#define NSTEP 127

// Fragment-ordered bf16 weights: entry (kt,nt,lane) = {b0, b1}
__device__ uint2 fBn[12*32*32];
__device__ uint2 fBs[12*32*32];
__device__ uint2 fBd[32*64*32];

// Boundary publish ring: [buf][b][tile][slot][256]
//   slot0 = site s0 (for left neighbor), slot1 = site s0+13 (for right neighbor)
//   entry: [0:64) hn, [64:128) hs, [128:256) hd
__device__ float g_pub[2][NB][NTILE][2][256];
__device__ int g_flag[NB*NTILE];

// ---- smem offsets (floats) ----
#define OFF_XIN 0                      // 64
#define OFF_O0  (OFF_XIN + 64)         // 16
#define OFF_O1  (OFF_O0 + 16)          // 16
#define OFF_CN  (OFF_O1 + 16)          // 1024
#define OFF_CS  (OFF_CN + 1024)        // 1024
#define OFF_CD  (OFF_CS + 1024)        // 2048
#define OFF_HDC (OFF_CD + 2048)        // 2048
#define OFF_NSF (OFF_HDC + 2048)       // 3072 uints (An @0, As @1536)
#define OFF_ADF (OFF_NSF + 3072)       // 4096 uints (Ad)
#define OFF_G   (OFF_ADF + 4096)       // 8192 (gn@0, gs@4096; gd overlay)
#define SMEM_FLOATS (OFF_G + 8192)

#define MMA4(c, a0,a1,a2,a3, b0,b1) \
  asm volatile("mma.sync.aligned.m16n8k16.row.col.f32.bf16.bf16.f32 " \
    "{%0,%1,%2,%3}, {%4,%5,%6,%7}, {%8,%9}, {%0,%1,%2,%3};" \
    : "+f"(c[0]), "+f"(c[1]), "+f"(c[2]), "+f"(c[3]) \
    : "r"(a0), "r"(a1), "r"(a2), "r"(a3), "r"(b0), "r"(b1))

__device__ __forceinline__ float sigm(float x) { return 1.f / (1.f + __expf(-x)); }

__device__ __forceinline__ uint packbf2(float a, float b) {
    __nv_bfloat16 ha = __float2bfloat16_rn(a);
    __nv_bfloat16 hb = __float2bfloat16_rn(b);
    __nv_bfloat16_raw ra = *(__nv_bfloat16_raw*)&ha;
    __nv_bfloat16_raw rb = *(__nv_bfloat16_raw*)&hb;
    return (uint)ra.x | ((uint)rb.x << 16);
}

// write one bf16 element into fragment-ordered array at logical (row r, col k)
__device__ __forceinline__ void store_frag(__nv_bfloat16* Fb, int r, int k, float v) {
    int kt = k >> 4, ec = k & 15;
    int reg = ((ec >> 3) << 1) | (r >> 3);
    int ln  = ((r & 7) << 2) | ((ec & 7) >> 1);
    int idx = ((((kt << 5) + ln) << 2) + reg) * 2 + (ec & 1);
    Fb[idx] = __float2bfloat16_rn(v);
}

__global__ void init_flags_kernel() {
    int i = blockIdx.x * blockDim.x + threadIdx.x;
    if (i < NB*NTILE) g_flag[i] = 0;
}

__global__ void repack_kernel(
    const float* __restrict__ nWh, const float* __restrict__ nWa, const float* __restrict__ nWb,
    const float* __restrict__ sWh, const float* __restrict__ sWa, const float* __restrict__ sWb,
    const float* __restrict__ dWx, const float* __restrict__ dWh,
    const float* __restrict__ dWa, const float* __restrict__ dWb)
{
    int idx = blockIdx.x * blockDim.x + threadIdx.x;
    if (idx < 32*64*32) {
        int lane = idx & 31, nt = (idx >> 5) & 63, kt = idx >> 11;
        int n = nt*8 + (lane >> 2);
        int k0 = kt*16 + (lane & 3)*2;
        float v[4];
        #pragma unroll
        for (int j = 0; j < 4; j++) {
            int kk = k0 + (j >> 1)*8 + (j & 1);
            float x;
            if      (kk < 128) x = dWx[kk*512 + n];
            else if (kk < 256) x = dWh[(kk-128)*512 + n];
            else if (kk < 384) x = dWa[(kk-256)*512 + n];
            else               x = dWb[(kk-384)*512 + n];
            v[j] = x;
        }
        fBd[idx] = make_uint2(packbf2(v[0], v[1]), packbf2(v[2], v[3]));
    }
    int idx2 = idx - 32*64*32;
    if (idx2 >= 0 && idx2 < 2*12*32*32) {
        int set = idx2 / (12*32*32);
        int e = idx2 % (12*32*32);
        int lane = e & 31, nt = (e >> 5) & 31, kt = e >> 10;
        int n = nt*8 + (lane >> 2);
        int k0 = kt*16 + (lane & 3)*2;
        const float* Wh = set ? sWh : nWh;
        const float* Wa = set ? sWa : nWa;
        const float* Wb = set ? sWb : nWb;
        float v[4];
        #pragma unroll
        for (int j = 0; j < 4; j++) {
            int kk = k0 + (j >> 1)*8 + (j & 1);
            float x;
            if      (kk < 64)  x = Wh[kk*256 + n];
            else if (kk < 128) x = Wa[(kk-64)*256 + n];
            else               x = Wb[(kk-128)*256 + n];
            v[j] = x;
        }
        (set ? fBs : fBn)[e] = make_uint2(packbf2(v[0], v[1]), packbf2(v[2], v[3]));
    }
}

__global__ void __launch_bounds__(TPB, 1) persistent_kernel(
    const float* __restrict__ xg,
    const float* __restrict__ nWx, const float* __restrict__ nb,
    const float* __restrict__ sWx, const float* __restrict__ sb,
    const float* __restrict__ db,
    const float* __restrict__ onW, const float* __restrict__ onb,
    const float* __restrict__ osW, const float* __restrict__ osb,
    float* __restrict__ out)
{
    extern __shared__ float sm[];
    float* xin = sm + OFF_XIN;   // [16][4]
    float* o0s = sm + OFF_O0;    // [16]
    float* o1s = sm + OFF_O1;
    float* cns = sm + OFF_CN;    // [16*64]
    float* css = sm + OFF_CS;
    float* cds = sm + OFF_CD;    // [16*128]
    float* hdc = sm + OFF_HDC;   // [16*128]
    uint*  nsU = (uint*)(sm + OFF_NSF);
    uint4* nsF4 = (uint4*)(sm + OFF_NSF);   // An: 384 uint4, As: +384
    uint*  adU = (uint*)(sm + OFF_ADF);
    uint4* AdF4 = (uint4*)(sm + OFF_ADF);   // 1024 uint4
    float* G = sm + OFF_G;       // gn@0, gs@4096; gd overlay@0

    const int tid  = threadIdx.x;
    const int w    = tid >> 5;
    const int lane = tid & 31;
    const int tile = blockIdx.x;      // 0..8
    const int bb   = blockIdx.y;      // 0..15
    const int s0   = tile * TS;

    __nv_bfloat16* AnB = (__nv_bfloat16*)nsU;
    __nv_bfloat16* AsB = AnB + 3072;
    __nv_bfloat16* AdB = (__nv_bfloat16*)adU;

    // ---- persistent-state init ----
    for (int i = tid; i < 3072; i += TPB) nsU[i] = 0;
    for (int i = tid; i < 4096; i += TPB) adU[i] = 0;
    for (int i = tid; i < 1024; i += TPB) { cns[i] = 0.f; css[i] = 0.f; }
    for (int i = tid; i < 2048; i += TPB) cds[i] = 0.f;
    __syncthreads();

    for (int t = 0; t < NSTEP; ++t) {
        // ---- P0: neighbor flag wait, halo import, xin load ----
        if (t > 0) {
            if (tid == 0 && tile > 0) {
                volatile int* f = &g_flag[bb*NTILE + tile - 1];
                while (*f < t) {}
                __threadfence();
            }
            if (tid == 32 && tile < NTILE-1) {
                volatile int* f = &g_flag[bb*NTILE + tile + 1];
                while (*f < t) {}
                __threadfence();
            }
        }
        __syncthreads();

        if (t > 0) {
            const int pb = (t - 1) & 1;
            if (tile > 0) {  // left neighbor's slot1 = site s0-2
                const float* L = g_pub[pb][bb][tile-1][1];
                for (int e = tid; e < 64; e += TPB) {
                    store_frag(AnB, 0, 128+e, L[e]);
                    store_frag(AsB, 0, 128+e, L[64+e]);
                }
                for (int e = tid - 64; ((unsigned)e) < 128u; e += TPB) {
                    store_frag(AdB, 0, 384+e, L[128+e]);
                }
            }
            if (tile < NTILE-1) {  // right neighbor's slot0 = site s0+15
                const float* R = g_pub[pb][bb][tile+1][0];
                for (int e = tid - 192; ((unsigned)e) < 64u; e += TPB) {
                    store_frag(AnB, 15, 64+e, R[e]);
                    store_frag(AsB, 15, 64+e, R[64+e]);
                }
                for (int e = tid - 256; ((unsigned)e) < 128u; e += TPB) {
                    store_frag(AdB, 15, 256+e, R[128+e]);
                }
            }
        }
        for (int i = tid - 384; ((unsigned)i) < (unsigned)(NS*4); i += TPB) {
            int r = i >> 2, sg = s0 - 1 + r;
            xin[i] = ((unsigned)sg < (unsigned)S)
                     ? xg[(((size_t)bb*T + t)*S + sg)*4 + (i & 3)] : 0.f;
        }
        __syncthreads();

        // ---- P1: ns GEMM + d GEMM part 1 (kt 8..31) ----
        float dacc[4][4];
        #pragma unroll
        for (int j = 0; j < 4; j++)
            #pragma unroll
            for (int c = 0; c < 4; c++) dacc[j][c] = 0.f;
        {
            const int set = w >> 3, grp = w & 7;
            const uint2* Bns = set ? fBs : fBn;
            const uint4* A0 = nsF4 + set*384;
            float acc[4][4];
            #pragma unroll
            for (int j = 0; j < 4; j++)
                #pragma unroll
                for (int c = 0; c < 4; c++) acc[j][c] = 0.f;

            for (int kt = 0; kt < 12; kt++) {
                uint4 a0 = A0[kt*32 + lane];
                #pragma unroll
                for (int j = 0; j < 4; j++) {
                    uint2 bv = __ldg(&Bns[(kt*32 + grp*4 + j)*32 + lane]);
                    MMA4(acc[j], a0.x, a0.y, a0.z, a0.w, bv.x, bv.y);
                }
            }
            int site0 = lane >> 2, cb = (lane & 3)*2;
            float* gg = G + set*4096;
            #pragma unroll
            for (int j = 0; j < 4; j++) {
                int c0 = (grp*4 + j)*8 + cb;
                *(float2*)&gg[site0*256 + c0]     = make_float2(acc[j][0], acc[j][1]);
                *(float2*)&gg[(site0+8)*256 + c0] = make_float2(acc[j][2], acc[j][3]);
            }
            for (int kt = 8; kt < 32; kt++) {
                uint4 a0 = AdF4[kt*32 + lane];
                #pragma unroll
                for (int j = 0; j < 4; j++) {
                    uint2 bv = __ldg(&fBd[(kt*64 + w*4 + j)*32 + lane]);
                    MMA4(dacc[j], a0.x, a0.y, a0.z, a0.w, bv.x, bv.y);
                }
            }
        }
        __syncthreads();

        // ---- P2: n/s cell updates; write next-step ns frags + Ad(k<128) + pubs ----
        for (int i = tid; i < NS*NH; i += TPB) {
            int r = i >> 6, e = i & 63;
            int sg = s0 - 1 + r;
            bool v = ((unsigned)sg < (unsigned)S);
            float* gn_ = G;
            float* gs_ = G + 4096;
            const float* xr = xin + r*4;
            float xr0 = xr[0], xr1 = xr[1], xr2 = xr[2], xr3 = xr[3];
            float hn_, hs_;
            {
                float ii = gn_[r*256 + e]      + nb[e]      + xr0*nWx[e]      + xr1*nWx[256+e]  + xr2*nWx[512+e];
                float ff = gn_[r*256 + 64+e]   + nb[64+e]   + xr0*nWx[64+e]   + xr1*nWx[320+e]  + xr2*nWx[576+e];
                float uu = gn_[r*256 + 128+e]  + nb[128+e]  + xr0*nWx[128+e]  + xr1*nWx[384+e]  + xr2*nWx[640+e];
                float oo = gn_[r*256 + 192+e]  + nb[192+e]  + xr0*nWx[192+e]  + xr1*nWx[448+e]  + xr2*nWx[704+e];
                float cp = cns[i];
                float c2 = sigm(ff)*cp + sigm(ii)*tanhf(uu);
                float hh = sigm(oo)*tanhf(c2);
                if (!v) { c2 = 0.f; hh = 0.f; }
                cns[i] = c2;
                hn_ = hh;
            }
            {
                float ii = gs_[r*256 + e]      + sb[e]      + xr3*sWx[e];
                float ff = gs_[r*256 + 64+e]   + sb[64+e]   + xr3*sWx[64+e];
                float uu = gs_[r*256 + 128+e]  + sb[128+e]  + xr3*sWx[128+e];
                float oo = gs_[r*256 + 192+e]  + sb[192+e]  + xr3*sWx[192+e];
                float cp = css[i];
                float c2 = sigm(ff)*cp + sigm(ii)*tanhf(uu);
                float hh = sigm(oo)*tanhf(c2);
                if (!v) { c2 = 0.f; hh = 0.f; }
                css[i] = c2;
                hs_ = hh;
            }
            // current-step d-GEMM inputs (k<128)
            store_frag(AdB, r, e, hn_);
            store_frag(AdB, r, 64+e, hs_);
            // next-step ns frags (3 shift positions each)
            store_frag(AnB, r, e, hn_);
            store_frag(AsB, r, e, hs_);
            if (r >= 1)  { store_frag(AnB, r-1, 64+e, hn_);  store_frag(AsB, r-1, 64+e, hs_); }
            if (r <= 14) { store_frag(AnB, r+1, 128+e, hn_); store_frag(AsB, r+1, 128+e, hs_); }
            // boundary publish
            if (r == 1)  { float* P = g_pub[t&1][bb][tile][0]; P[e] = hn_; P[64+e] = hs_; }
            if (r == 14) { float* P = g_pub[t&1][bb][tile][1]; P[e] = hn_; P[64+e] = hs_; }
        }
        __syncthreads();

        // ---- P3: d GEMM part 2 (kt 0..7), write gd (overlays gn/gs) ----
        for (int kt = 0; kt < 8; kt++) {
            uint4 a0 = AdF4[kt*32 + lane];
            #pragma unroll
            for (int j = 0; j < 4; j++) {
                uint2 bv = __ldg(&fBd[(kt*64 + w*4 + j)*32 + lane]);
                MMA4(dacc[j], a0.x, a0.y, a0.z, a0.w, bv.x, bv.y);
            }
        }
        __syncthreads();
        {
            int site0 = lane >> 2, cb = (lane & 3)*2;
            float* gdp = G;
            #pragma unroll
            for (int j = 0; j < 4; j++) {
                int c0 = (w*4 + j)*8 + cb;
                *(float2*)&gdp[site0*512 + c0]     = make_float2(dacc[j][0], dacc[j][1]);
                *(float2*)&gdp[(site0+8)*512 + c0] = make_float2(dacc[j][2], dacc[j][3]);
            }
        }
        __syncthreads();

        // ---- P4: d cell update; write hdc + next-step Ad(k>=128) + pubs ----
        for (int i = tid; i < NS*DH; i += TPB) {
            int r = i >> 7, e = i & 127;
            int sg = s0 - 1 + r;
            bool v = ((unsigned)sg < (unsigned)S);
            float* gdp = G;
            float ii = gdp[r*512 + e]       + db[e];
            float ff = gdp[r*512 + 128 + e] + db[128+e];
            float uu = gdp[r*512 + 256 + e] + db[256+e];
            float oo = gdp[r*512 + 384 + e] + db[384+e];
            float cp = cds[i];
            float c2 = sigm(ff)*cp + sigm(ii)*tanhf(uu);
            float hh = sigm(oo)*tanhf(c2);
            if (!v) { c2 = 0.f; hh = 0.f; }
            cds[i] = c2;
            hdc[i] = hh;
            store_frag(AdB, r, 128+e, hh);
            if (r >= 1)  store_frag(AdB, r-1, 256+e, hh);
            if (r <= 14) store_frag(AdB, r+1, 384+e, hh);
            if (r == 1)  g_pub[t&1][bb][tile][0][128+e] = hh;
            if (r == 14) g_pub[t&1][bb][tile][1][128+e] = hh;
        }
        __syncthreads();

        // flag release (all pubs of step t complete)
        if (tid == 0) {
            __threadfence();
            *(volatile int*)&g_flag[bb*NTILE + tile] = t + 1;
        }

        // ---- P5: output heads (32 warp-tasks over 16 warps) ----
        for (int task = w; task < 32; task += 16) {
            int which = task >> 4;
            int r = task & 15;
            const float* W = which ? osW : onW;
            float a = 0.f;
            #pragma unroll
            for (int kk = lane; kk < DH; kk += 32) a += hdc[r*DH + kk] * W[kk];
            #pragma unroll
            for (int d = 16; d >= 1; d >>= 1) a += __shfl_xor_sync(0xffffffffu, a, d);
            if (lane == 0) {
                if (which) o1s[r] = a + osb[0];
                else       o0s[r] = a + onb[0];
            }
        }
        __syncthreads();

        // ---- P6: write outputs for t >= 20 ----
        if (t >= 20 && tid >= 1 && tid <= TS) {
            int rr = tid;
            int sg = s0 + rr - 1;
            if (sg < S) {
                float o0 = o0s[rr];
                float o1 = o1s[rr];
                float inflow, spd;
                if (sg == 0) {
                    inflow = xg[(((size_t)bb*T + (t+1))*S + 0)*4 + 1];
                    spd    = xg[(((size_t)bb*T + (t+1))*S + 0)*4 + 3];
                } else {
                    inflow = o0s[rr-1];
                    spd    = o1;
                }
                float numc = xin[rr*4 + 2] + inflow - o0;
                float* o = out + ((((size_t)bb*TOUT) + (t - 20))*S + sg)*4;
                o[0] = o0; o[1] = inflow; o[2] = numc; o[3] = spd;
            }
        }
        __syncthreads();
    }
}

extern "C" void kernel_launch(void* const* d_in, const int* in_sizes, int n_in,
                              void* d_out, int out_size) {
    const float* xg  = (const float*)d_in[0];
    const float* nWx = (const float*)d_in[1];
    const float* nWh = (const float*)d_in[2];
    const float* nWa = (const float*)d_in[3];
    const float* nWb = (const float*)d_in[4];
    const float* nb  = (const float*)d_in[5];
    const float* sWx = (const float*)d_in[6];
    const float* sWh = (const float*)d_in[7];
    const float* sWa = (const float*)d_in[8];
    const float* sWb = (const float*)d_in[9];
    const float* sb  = (const float*)d_in[10];
    const float* dWx = (const float*)d_in[11];
    const float* dWh = (const float*)d_in[12];
    const float* dWa = (const float*)d_in[13];
    const float* dWb = (const float*)d_in[14];
    const float* db  = (const float*)d_in[15];
    const float* onW = (const float*)d_in[16];
    const float* onb = (const float*)d_in[17];
    const float* osW = (const float*)d_in[18];
    const float* osb = (const float*)d_in[19];
    float* out = (float*)d_out;

    (void)in_sizes; (void)n_in; (void)out_size;

    const int smem_bytes = SMEM_FLOATS * (int)sizeof(float);
    cudaFuncSetAttribute(persistent_kernel,
                         cudaFuncAttributeMaxDynamicSharedMemorySize, smem_bytes);

    init_flags_kernel<<<1, 256>>>();
    int repack_threads = 32*64*32 + 2*12*32*32;
    repack_kernel<<<(repack_threads + 255) / 256, 256>>>(
        nWh, nWa, nWb, sWh, sWa, sWb, dWx, dWh, dWa, dWb);

    dim3 grid(NTILE, NB);
    persistent_kernel<<<grid, TPB, smem_bytes>>>(
        xg, nWx, nb, sWx, sb, db, onW, onb, osW, osb, out);
}

// round 9
// speedup vs baseline: 2.1597x; 1.3169x over previous
#include <cuda_runtime.h>
#include <cuda_bf16.h>
#include <math.h>

typedef unsigned int uint;

#define S 128
#define T 128
#define NB 16
#define NH 64
#define DH 128
#define TS 15
#define NS 16
#define NTILE 9
#define TPB 512
#define TOUT 107
#define NSTEP 127

// Fragment-ordered bf16 weights, N-dim gate-interleaved:
// new col n' = (e>>3)*32 + gate*8 + (e&7)
__device__ uint2 fBn[12*32*32];
__device__ uint2 fBs[12*32*32];
__device__ uint2 fBd[32*64*32];

// Boundary publish ring: [buf][b][tile][slot][256]
// slot0 = site s0, slot1 = site s0+13; [0:64) hn, [64:128) hs, [128:256) hd
__device__ float g_pub[2][NB][NTILE][2][256];
__device__ int g_flag[NB*NTILE];

// ---- smem offsets (floats) ----
#define OFF_XIN 0                      // 64
#define OFF_O0  (OFF_XIN + 64)         // 16
#define OFF_O1  (OFF_O0 + 16)          // 16
#define OFF_HDC (OFF_O1 + 16)          // 2048
#define OFF_NSF (OFF_HDC + 2048)       // 3072 uints: An@0, As@1536
#define OFF_ADF (OFF_NSF + 3072)       // 4096 uints
#define SMEM_FLOATS (OFF_ADF + 4096)

#define MMA4(c, a0,a1,a2,a3, b0,b1) \
  asm volatile("mma.sync.aligned.m16n8k16.row.col.f32.bf16.bf16.f32 " \
    "{%0,%1,%2,%3}, {%4,%5,%6,%7}, {%8,%9}, {%0,%1,%2,%3};" \
    : "+f"(c[0]), "+f"(c[1]), "+f"(c[2]), "+f"(c[3]) \
    : "r"(a0), "r"(a1), "r"(a2), "r"(a3), "r"(b0), "r"(b1))

__device__ __forceinline__ float tanhap(float x) {
    float y;
    asm("tanh.approx.f32 %0, %1;" : "=f"(y) : "f"(x));
    return y;
}
__device__ __forceinline__ float sigm(float x) {
    return fmaf(tanhap(0.5f*x), 0.5f, 0.5f);
}

__device__ __forceinline__ uint packbf2(float a, float b) {
    __nv_bfloat16 ha = __float2bfloat16_rn(a);
    __nv_bfloat16 hb = __float2bfloat16_rn(b);
    __nv_bfloat16_raw ra = *(__nv_bfloat16_raw*)&ha;
    __nv_bfloat16_raw rb = *(__nv_bfloat16_raw*)&hb;
    return (uint)ra.x | ((uint)rb.x << 16);
}

// scalar bf16 store into fragment-ordered array at logical (row r, col k)
__device__ __forceinline__ void store_frag(__nv_bfloat16* Fb, int r, int k, float v) {
    int kt = k >> 4, ec = k & 15;
    int reg = ((ec >> 3) << 1) | (r >> 3);
    int ln  = ((r & 7) << 2) | ((ec & 7) >> 1);
    int idx = ((((kt << 5) + ln) << 2) + reg) * 2 + (ec & 1);
    Fb[idx] = __float2bfloat16_rn(v);
}
// packed pair store (k even): writes bf16 elements (r,k) and (r,k+1)
__device__ __forceinline__ void store_frag2(uint* Fu, int r, int k, uint v) {
    int kt = k >> 4, ec = k & 15;
    int reg = ((ec >> 3) << 1) | (r >> 3);
    int ln  = ((r & 7) << 2) | ((ec & 7) >> 1);
    Fu[(((kt << 5) + ln) << 2) + reg] = v;
}

__global__ void init_flags_kernel() {
    int i = blockIdx.x * blockDim.x + threadIdx.x;
    if (i < NB*NTILE) g_flag[i] = 0;
}

__global__ void repack_kernel(
    const float* __restrict__ nWh, const float* __restrict__ nWa, const float* __restrict__ nWb,
    const float* __restrict__ sWh, const float* __restrict__ sWa, const float* __restrict__ sWb,
    const float* __restrict__ dWx, const float* __restrict__ dWh,
    const float* __restrict__ dWa, const float* __restrict__ dWb)
{
    int idx = blockIdx.x * blockDim.x + threadIdx.x;
    if (idx < 32*64*32) {
        int lane = idx & 31, nt = (idx >> 5) & 63, kt = idx >> 11;
        int nprime = nt*8 + (lane >> 2);
        int e = ((nprime >> 5) << 3) | (nprime & 7);
        int g = (nprime >> 3) & 3;
        int n = g*128 + e;
        int k0 = kt*16 + (lane & 3)*2;
        float v[4];
        #pragma unroll
        for (int j = 0; j < 4; j++) {
            int kk = k0 + (j >> 1)*8 + (j & 1);
            float x;
            if      (kk < 128) x = dWx[kk*512 + n];
            else if (kk < 256) x = dWh[(kk-128)*512 + n];
            else if (kk < 384) x = dWa[(kk-256)*512 + n];
            else               x = dWb[(kk-384)*512 + n];
            v[j] = x;
        }
        fBd[idx] = make_uint2(packbf2(v[0], v[1]), packbf2(v[2], v[3]));
    }
    int idx2 = idx - 32*64*32;
    if (idx2 >= 0 && idx2 < 2*12*32*32) {
        int set = idx2 / (12*32*32);
        int e_ = idx2 % (12*32*32);
        int lane = e_ & 31, nt = (e_ >> 5) & 31, kt = e_ >> 10;
        int nprime = nt*8 + (lane >> 2);
        int e = ((nprime >> 5) << 3) | (nprime & 7);
        int g = (nprime >> 3) & 3;
        int n = g*64 + e;
        int k0 = kt*16 + (lane & 3)*2;
        const float* Wh = set ? sWh : nWh;
        const float* Wa = set ? sWa : nWa;
        const float* Wb = set ? sWb : nWb;
        float v[4];
        #pragma unroll
        for (int j = 0; j < 4; j++) {
            int kk = k0 + (j >> 1)*8 + (j & 1);
            float x;
            if      (kk < 64)  x = Wh[kk*256 + n];
            else if (kk < 128) x = Wa[(kk-64)*256 + n];
            else               x = Wb[(kk-128)*256 + n];
            v[j] = x;
        }
        (set ? fBs : fBn)[e_] = make_uint2(packbf2(v[0], v[1]), packbf2(v[2], v[3]));
    }
}

__global__ void __launch_bounds__(TPB, 1) persistent_kernel(
    const float* __restrict__ xg,
    const float* __restrict__ nWx, const float* __restrict__ nb,
    const float* __restrict__ sWx, const float* __restrict__ sb,
    const float* __restrict__ db,
    const float* __restrict__ onW, const float* __restrict__ onb,
    const float* __restrict__ osW, const float* __restrict__ osb,
    float* __restrict__ out)
{
    extern __shared__ float sm[];
    float* xin = sm + OFF_XIN;   // [16][4]
    float* o0s = sm + OFF_O0;
    float* o1s = sm + OFF_O1;
    float* hdc = sm + OFF_HDC;   // [16*128]
    uint*  nsU = (uint*)(sm + OFF_NSF);   // An@0 (1536), As@1536
    uint4* nsF4 = (uint4*)(sm + OFF_NSF);
    uint*  adU = (uint*)(sm + OFF_ADF);   // 4096
    uint4* AdF4 = (uint4*)(sm + OFF_ADF);

    const int tid  = threadIdx.x;
    const int w    = tid >> 5;
    const int lane = tid & 31;
    const int tile = blockIdx.x;
    const int bb   = blockIdx.y;
    const int s0   = tile * TS;

    const int set = w >> 3, grp = w & 7;   // ns GEMM role
    const int r0 = lane >> 2, r1 = r0 + 8;
    const int e0  = grp*8 + (lane & 3)*2;  // ns e-slice
    const int e0d = w*8   + (lane & 3)*2;  // d  e-slice
    const bool v0 = ((unsigned)(s0 - 1 + r0) < (unsigned)S);
    const bool v1 = ((unsigned)(s0 - 1 + r1) < (unsigned)S);

    __nv_bfloat16* AnB = (__nv_bfloat16*)nsU;
    __nv_bfloat16* AsB = AnB + 3072;
    __nv_bfloat16* AdB = (__nv_bfloat16*)adU;
    uint* AnU = nsU;
    uint* AsU = nsU + 1536;

    // register-resident c-states (static lane ownership)
    float creg[4] = {0.f, 0.f, 0.f, 0.f};   // cn (warps 0-7) / cs (warps 8-15)
    float cd[4]   = {0.f, 0.f, 0.f, 0.f};

    for (int i = tid; i < 3072; i += TPB) nsU[i] = 0;
    for (int i = tid; i < 4096; i += TPB) adU[i] = 0;
    __syncthreads();

    for (int t = 0; t < NSTEP; ++t) {
        // ---- P0: neighbor waits, halo imports, xin ----
        if (t > 0) {
            if (tid == 0 && tile > 0) {
                volatile int* f = &g_flag[bb*NTILE + tile - 1];
                while (*f < t) {}
                __threadfence();
            }
            if (tid == 32 && tile < NTILE-1) {
                volatile int* f = &g_flag[bb*NTILE + tile + 1];
                while (*f < t) {}
                __threadfence();
            }
        }
        __syncthreads();

        if (t > 0) {
            const int pb = (t - 1) & 1;
            if (tile > 0) {  // left neighbor slot1 = site s0-2
                const float* L = g_pub[pb][bb][tile-1][1];
                for (int e = tid; e < 64; e += TPB) {
                    store_frag(AnB, 0, 128+e, L[e]);
                    store_frag(AsB, 0, 128+e, L[64+e]);
                }
                for (int e = tid - 64; ((unsigned)e) < 128u; e += TPB)
                    store_frag(AdB, 0, 384+e, L[128+e]);
            }
            if (tile < NTILE-1) {  // right neighbor slot0 = site s0+15
                const float* R = g_pub[pb][bb][tile+1][0];
                for (int e = tid - 192; ((unsigned)e) < 64u; e += TPB) {
                    store_frag(AnB, 15, 64+e, R[e]);
                    store_frag(AsB, 15, 64+e, R[64+e]);
                }
                for (int e = tid - 256; ((unsigned)e) < 128u; e += TPB)
                    store_frag(AdB, 15, 256+e, R[128+e]);
            }
        }
        for (int i = tid - 384; ((unsigned)i) < (unsigned)(NS*4); i += TPB) {
            int r = i >> 2, sg = s0 - 1 + r;
            xin[i] = ((unsigned)sg < (unsigned)S)
                     ? xg[(((size_t)bb*T + t)*S + sg)*4 + (i & 3)] : 0.f;
        }
        __syncthreads();

        // ---- P1: ns mma + d1 mma + ns cell (registers) ----
        float acc[4][4], dacc[4][4];
        #pragma unroll
        for (int j = 0; j < 4; j++)
            #pragma unroll
            for (int c = 0; c < 4; c++) { acc[j][c] = 0.f; dacc[j][c] = 0.f; }
        {
            const uint2* Bns = set ? fBs : fBn;
            const uint4* A0 = nsF4 + set*384;
            for (int kt = 0; kt < 12; kt++) {
                uint4 a0 = A0[kt*32 + lane];
                #pragma unroll
                for (int j = 0; j < 4; j++) {
                    uint2 bv = __ldg(&Bns[(kt*32 + grp*4 + j)*32 + lane]);
                    MMA4(acc[j], a0.x, a0.y, a0.z, a0.w, bv.x, bv.y);
                }
            }
            for (int kt = 8; kt < 32; kt++) {
                uint4 a0 = AdF4[kt*32 + lane];
                #pragma unroll
                for (int j = 0; j < 4; j++) {
                    uint2 bv = __ldg(&fBd[(kt*64 + w*4 + j)*32 + lane]);
                    MMA4(dacc[j], a0.x, a0.y, a0.z, a0.w, bv.x, bv.y);
                }
            }
        }
        // x-input + bias fold (fp32 exact), then cell update in registers
        float hv[4];
        {
            float xA[4], xB[4];
            #pragma unroll
            for (int k = 0; k < 4; k++) { xA[k] = xin[r0*4 + k]; xB[k] = xin[r1*4 + k]; }
            if (set == 0) {
                #pragma unroll
                for (int g = 0; g < 4; g++) {
                    int col = g*64 + e0;
                    float2 b2 = *(const float2*)&nb[col];
                    float2 w0 = *(const float2*)&nWx[col];
                    float2 w1 = *(const float2*)&nWx[256 + col];
                    float2 w2 = *(const float2*)&nWx[512 + col];
                    acc[g][0] += b2.x + xA[0]*w0.x + xA[1]*w1.x + xA[2]*w2.x;
                    acc[g][1] += b2.y + xA[0]*w0.y + xA[1]*w1.y + xA[2]*w2.y;
                    acc[g][2] += b2.x + xB[0]*w0.x + xB[1]*w1.x + xB[2]*w2.x;
                    acc[g][3] += b2.y + xB[0]*w0.y + xB[1]*w1.y + xB[2]*w2.y;
                }
            } else {
                #pragma unroll
                for (int g = 0; g < 4; g++) {
                    int col = g*64 + e0;
                    float2 b2 = *(const float2*)&sb[col];
                    float2 w3 = *(const float2*)&sWx[col];
                    acc[g][0] += b2.x + xA[3]*w3.x;
                    acc[g][1] += b2.y + xA[3]*w3.y;
                    acc[g][2] += b2.x + xB[3]*w3.x;
                    acc[g][3] += b2.y + xB[3]*w3.y;
                }
            }
            #pragma unroll
            for (int c = 0; c < 4; c++) {
                bool v = (c < 2) ? v0 : v1;
                float c2 = sigm(acc[1][c])*creg[c] + sigm(acc[0][c])*tanhap(acc[2][c]);
                float hh = sigm(acc[3][c])*tanhap(c2);
                if (!v) { c2 = 0.f; hh = 0.f; }
                creg[c] = c2;
                hv[c] = hh;
            }
            // current-step d A-matrix (kt 0..7): k = set*64 + e
            store_frag2(adU, r0, set*64 + e0, packbf2(hv[0], hv[1]));
            store_frag2(adU, r1, set*64 + e0, packbf2(hv[2], hv[3]));
            // boundary publish (n/s parts)
            if (r0 == 1)  { float* P = g_pub[t&1][bb][tile][0]; P[set*64 + e0] = hv[0]; P[set*64 + e0 + 1] = hv[1]; }
            if (r1 == 14) { float* P = g_pub[t&1][bb][tile][1]; P[set*64 + e0] = hv[2]; P[set*64 + e0 + 1] = hv[3]; }
        }
        __syncthreads();

        // ---- P2: d2 mma + d cell (registers) + all next-step frag stores ----
        for (int kt = 0; kt < 8; kt++) {
            uint4 a0 = AdF4[kt*32 + lane];
            #pragma unroll
            for (int j = 0; j < 4; j++) {
                uint2 bv = __ldg(&fBd[(kt*64 + w*4 + j)*32 + lane]);
                MMA4(dacc[j], a0.x, a0.y, a0.z, a0.w, bv.x, bv.y);
            }
        }
        {
            #pragma unroll
            for (int g = 0; g < 4; g++) {
                float2 b2 = *(const float2*)&db[g*128 + e0d];
                dacc[g][0] += b2.x; dacc[g][1] += b2.y;
                dacc[g][2] += b2.x; dacc[g][3] += b2.y;
            }
            float hdv[4];
            #pragma unroll
            for (int c = 0; c < 4; c++) {
                bool v = (c < 2) ? v0 : v1;
                float c2 = sigm(dacc[1][c])*cd[c] + sigm(dacc[0][c])*tanhap(dacc[2][c]);
                float hh = sigm(dacc[3][c])*tanhap(c2);
                if (!v) { c2 = 0.f; hh = 0.f; }
                cd[c] = c2;
                hdv[c] = hh;
            }
            *(float2*)&hdc[r0*128 + e0d] = make_float2(hdv[0], hdv[1]);
            *(float2*)&hdc[r1*128 + e0d] = make_float2(hdv[2], hdv[3]);
            uint p01 = packbf2(hdv[0], hdv[1]);
            uint p23 = packbf2(hdv[2], hdv[3]);
            store_frag2(adU, r0, 128 + e0d, p01);
            store_frag2(adU, r1, 128 + e0d, p23);
            if (r0 >= 1)  store_frag2(adU, r0 - 1, 256 + e0d, p01);
            store_frag2(adU, r1 - 1, 256 + e0d, p23);
            store_frag2(adU, r0 + 1, 384 + e0d, p01);
            if (r1 <= 14) store_frag2(adU, r1 + 1, 384 + e0d, p23);
            if (r0 == 1)  { float* P = g_pub[t&1][bb][tile][0]; P[128 + e0d] = hdv[0]; P[128 + e0d + 1] = hdv[1]; }
            if (r1 == 14) { float* P = g_pub[t&1][bb][tile][1]; P[128 + e0d] = hdv[2]; P[128 + e0d + 1] = hdv[3]; }
            // next-step ns A fragments from hv
            uint q01 = packbf2(hv[0], hv[1]);
            uint q23 = packbf2(hv[2], hv[3]);
            uint* F = set ? AsU : AnU;
            store_frag2(F, r0, e0, q01);
            store_frag2(F, r1, e0, q23);
            if (r0 >= 1)  store_frag2(F, r0 - 1, 64 + e0, q01);
            store_frag2(F, r1 - 1, 64 + e0, q23);
            store_frag2(F, r0 + 1, 128 + e0, q01);
            if (r1 <= 14) store_frag2(F, r1 + 1, 128 + e0, q23);
        }
        __syncthreads();

        // flag release (all pubs done)
        if (tid == 0) {
            __threadfence();
            *(volatile int*)&g_flag[bb*NTILE + tile] = t + 1;
        }

        // ---- P3: output heads ----
        for (int task = w; task < 32; task += 16) {
            int which = task >> 4;
            int r = task & 15;
            const float* W = which ? osW : onW;
            float a = 0.f;
            #pragma unroll
            for (int kk = lane; kk < DH; kk += 32) a += hdc[r*DH + kk] * W[kk];
            #pragma unroll
            for (int d = 16; d >= 1; d >>= 1) a += __shfl_xor_sync(0xffffffffu, a, d);
            if (lane == 0) {
                if (which) o1s[r] = a + osb[0];
                else       o0s[r] = a + onb[0];
            }
        }
        __syncthreads();

        // ---- P4: write outputs for t >= 20 ----
        if (t >= 20 && tid >= 1 && tid <= TS) {
            int rr = tid;
            int sg = s0 + rr - 1;
            if (sg < S) {
                float o0 = o0s[rr];
                float o1 = o1s[rr];
                float inflow, spd;
                if (sg == 0) {
                    inflow = xg[(((size_t)bb*T + (t+1))*S + 0)*4 + 1];
                    spd    = xg[(((size_t)bb*T + (t+1))*S + 0)*4 + 3];
                } else {
                    inflow = o0s[rr-1];
                    spd    = o1;
                }
                float numc = xin[rr*4 + 2] + inflow - o0;
                float* o = out + ((((size_t)bb*TOUT) + (t - 20))*S + sg)*4;
                o[0] = o0; o[1] = inflow; o[2] = numc; o[3] = spd;
            }
        }
        __syncthreads();
    }
}

extern "C" void kernel_launch(void* const* d_in, const int* in_sizes, int n_in,
                              void* d_out, int out_size) {
    const float* xg  = (const float*)d_in[0];
    const float* nWx = (const float*)d_in[1];
    const float* nWh = (const float*)d_in[2];
    const float* nWa = (const float*)d_in[3];
    const float* nWb = (const float*)d_in[4];
    const float* nb  = (const float*)d_in[5];
    const float* sWx = (const float*)d_in[6];
    const float* sWh = (const float*)d_in[7];
    const float* sWa = (const float*)d_in[8];
    const float* sWb = (const float*)d_in[9];
    const float* sb  = (const float*)d_in[10];
    const float* dWx = (const float*)d_in[11];
    const float* dWh = (const float*)d_in[12];
    const float* dWa = (const float*)d_in[13];
    const float* dWb = (const float*)d_in[14];
    const float* db  = (const float*)d_in[15];
    const float* onW = (const float*)d_in[16];
    const float* onb = (const float*)d_in[17];
    const float* osW = (const float*)d_in[18];
    const float* osb = (const float*)d_in[19];
    float* out = (float*)d_out;

    (void)in_sizes; (void)n_in; (void)out_size;

    const int smem_bytes = SMEM_FLOATS * (int)sizeof(float);
    cudaFuncSetAttribute(persistent_kernel,
                         cudaFuncAttributeMaxDynamicSharedMemorySize, smem_bytes);

    init_flags_kernel<<<1, 256>>>();
    int repack_threads = 32*64*32 + 2*12*32*32;
    repack_kernel<<<(repack_threads + 255) / 256, 256>>>(
        nWh, nWa, nWb, sWh, sWa, sWb, dWx, dWh, dWa, dWb);

    dim3 grid(NTILE, NB);
    persistent_kernel<<<grid, TPB, smem_bytes>>>(
        xg, nWx, nb, sWx, sb, db, onW, onb, osW, osb, out);
}